// round 6
// baseline (speedup 1.0000x reference)
#include <cuda_runtime.h>
#include <cuda_fp16.h>
#include <math.h>

#define NMAX 100000
#define EMAX 1310720
#define DD 64
typedef unsigned long long u64;

// -------- persistent scratch (device globals; no allocation allowed) --------
__device__ __align__(16) __half g_Ph[NMAX * 32];     // x @ Wp1[:64]  (fp16)
__device__ __align__(16) __half g_Qh[NMAX * 32];     // x @ Wn1[:64]  (fp16)
__device__ __align__(16) __half g_accPh[NMAX * 32];  // fp16 accumulators
__device__ __align__(16) __half g_accNh[NMAX * 32];
__device__ __align__(16) __half g_xpnh[NMAX * 64];   // [xp | xn] fp16
__device__ __align__(16) __half g_accP2h[NMAX * 64]; // pos: [sum xp | sum xn]
__device__ __align__(16) __half g_accN2h[NMAX * 64]; // neg: [sum xn | sum xp]
__device__ __align__(16) float  g_cntp[NMAX];
__device__ __align__(16) float  g_cntn[NMAX];
__device__ __align__(16) int2   g_es[EMAX];          // {src, dst or ~dst(neg)}

// ------------------------------ tiny helpers --------------------------------
__device__ __forceinline__ void red_v4h(__half* p, uint4 v) {
    asm volatile("red.global.add.noftz.v4.f16x2 [%0], {%1,%2,%3,%4};"
                 :: "l"(p), "r"(v.x), "r"(v.y), "r"(v.z), "r"(v.w)
                 : "memory");
}
__device__ __forceinline__ u64 fma2(u64 a, u64 b, u64 c) {
    u64 d;
    asm("fma.rn.f32x2 %0, %1, %2, %3;" : "=l"(d) : "l"(a), "l"(b), "l"(c));
    return d;
}
__device__ __forceinline__ u64 dup2(float a) {
    u64 r;
    asm("mov.b64 %0, {%1, %1};" : "=l"(r) : "f"(a));
    return r;
}
__device__ __forceinline__ float2 unpack2(u64 v) {
    float2 r;
    asm("mov.b64 {%0, %1}, %2;" : "=f"(r.x), "=f"(r.y) : "l"(v));
    return r;
}
__device__ __forceinline__ void h8tof(uint4 v, float* o) {
    const __half2* h = (const __half2*)&v;
#pragma unroll
    for (int j = 0; j < 4; j++) {
        float2 f = __half22float2(h[j]);
        o[2 * j] = f.x;
        o[2 * j + 1] = f.y;
    }
}
__device__ __forceinline__ unsigned pack_h2(float a, float b) {
    __half2 h = __floats2half2_rn(a, b);
    return *(unsigned*)&h;
}
// acc[16] covers 32 outputs; wrow = 32 consecutive floats in smem
__device__ __forceinline__ void fma_row32(u64* acc, const float* wrow, u64 s2) {
#pragma unroll
    for (int q = 0; q < 8; q++) {
        ulonglong2 w = *(const ulonglong2*)(wrow + 4 * q);
        acc[2 * q]     = fma2(s2, w.x, acc[2 * q]);
        acc[2 * q + 1] = fma2(s2, w.y, acc[2 * q + 1]);
    }
}

// ------------------- init: pack edges + zero accumulators -------------------
__global__ void k_init(const int* __restrict__ ei, int E, int n) {
    int i = blockIdx.x * blockDim.x + threadIdx.x;
    int stride = gridDim.x * blockDim.x;
    for (int e = i; e < E; e += stride) {
        long eb = 3L * e;
        int s  = __ldg(ei + eb);
        int d  = __ldg(ei + eb + 1);
        int sg = __ldg(ei + eb + 2);
        g_es[e] = make_int2(s, (sg > 0) ? d : ~d);
    }
    uint4 z4 = make_uint4(0u, 0u, 0u, 0u);
    size_t nh = (size_t)n * 4;
    for (size_t j = i; j < nh; j += stride) {
        ((uint4*)g_accPh)[j] = z4;
        ((uint4*)g_accNh)[j] = z4;
    }
    size_t nd = (size_t)n * 8;
    for (size_t j = i; j < nd; j += stride) {
        ((uint4*)g_accP2h)[j] = z4;
        ((uint4*)g_accN2h)[j] = z4;
    }
    size_t nc = (size_t)n / 4;
    for (size_t j = i; j < nc; j += stride) {
        ((uint4*)g_cntp)[j] = z4;
        ((uint4*)g_cntn)[j] = z4;
    }
}

// --------- projection (pair-split): half0 -> P = x@Wp1[:64], half1 -> Q -----
__global__ void __launch_bounds__(256)
k_proj1(const float* __restrict__ x,
        const float* __restrict__ Wp1, const float* __restrict__ Wn1,
        int n_nodes) {
    __shared__ __align__(16) float Ws[2][64 * 32];
    int tid = threadIdx.x;
    for (int i = tid; i < 64 * 32; i += blockDim.x) {
        Ws[0][i] = Wp1[i];
        Ws[1][i] = Wn1[i];
    }
    __syncthreads();

    long idx = (long)blockIdx.x * blockDim.x + tid;
    int n = (int)(idx >> 1), half = (int)(idx & 1);
    if (n >= n_nodes) return;
    const float* W = Ws[half];

    const float4* x4 = (const float4*)x + (size_t)n * 16;
    u64 a[16];
#pragma unroll
    for (int jp = 0; jp < 16; jp++) a[jp] = 0ull;
    for (int kc = 0; kc < 16; kc++) {
        float4 xv = x4[kc];
        const float* xa = (const float*)&xv;
#pragma unroll
        for (int e = 0; e < 4; e++)
            fma_row32(a, W + (kc * 4 + e) * 32, dup2(xa[e]));
    }
    uint4* dst = (uint4*)(half ? g_Qh : g_Ph) + (size_t)n * 4;
#pragma unroll
    for (int q = 0; q < 4; q++) {
        uint4 u;
        float2 a0 = unpack2(a[4 * q]),     a1 = unpack2(a[4 * q + 1]);
        float2 a2 = unpack2(a[4 * q + 2]), a3 = unpack2(a[4 * q + 3]);
        u.x = pack_h2(a0.x, a0.y); u.y = pack_h2(a1.x, a1.y);
        u.z = pack_h2(a2.x, a2.y); u.w = pack_h2(a3.x, a3.y);
        dst[q] = u;
    }
}

// --------------------------- layer-1 aggregation ----------------------------
// 2 edges per thread; 4 chunk-threads per edge pair.
__global__ void k_edge1(int E, long total) {
    long idx = (long)blockIdx.x * blockDim.x + threadIdx.x;
    if (idx >= total) return;
    int p = (int)(idx >> 2);
    int c = (int)(idx & 3);
    int e0 = 2 * p;
    int4 es = __ldg((const int4*)g_es + p);
    bool has1 = (e0 + 1 < E);

    int s0 = es.x, d0 = es.y;
    bool pos0 = (d0 >= 0);
    if (!pos0) d0 = ~d0;
    int s1 = es.z, d1 = es.w;
    bool pos1 = (d1 >= 0);
    if (!pos1) d1 = ~d1;

    uint4 v0 = *((const uint4*)(pos0 ? g_Ph : g_Qh) + (size_t)s0 * 4 + c);
    uint4 v1;
    if (has1) v1 = *((const uint4*)(pos1 ? g_Ph : g_Qh) + (size_t)s1 * 4 + c);

    red_v4h((pos0 ? g_accPh : g_accNh) + (size_t)d0 * 32 + c * 8, v0);
    if (c == 0) atomicAdd(pos0 ? (g_cntp + d0) : (g_cntn + d0), 1.0f);
    if (has1) {
        red_v4h((pos1 ? g_accPh : g_accNh) + (size_t)d1 * 32 + c * 8, v1);
        if (c == 0) atomicAdd(pos1 ? (g_cntp + d1) : (g_cntn + d1), 1.0f);
    }
}

// ---------- node layer 1 (pair-split): half0 -> xp, half1 -> xn -------------
__global__ void __launch_bounds__(256)
k_node1(const float* __restrict__ x,
        const float* __restrict__ Wp1, const float* __restrict__ bp1,
        const float* __restrict__ Wn1, const float* __restrict__ bn1,
        int n_nodes) {
    __shared__ __align__(16) float Ws[2][64 * 32];
    __shared__ __align__(16) float bs[2][32];
    int tid = threadIdx.x;
    for (int i = tid; i < 64 * 32; i += blockDim.x) {
        Ws[0][i] = Wp1[64 * 32 + i];   // rows 64..127
        Ws[1][i] = Wn1[64 * 32 + i];
    }
    if (tid < 32) { bs[0][tid] = bp1[tid]; bs[1][tid] = bn1[tid]; }
    __syncthreads();

    long idx = (long)blockIdx.x * blockDim.x + tid;
    int n = (int)(idx >> 1), half = (int)(idx & 1);
    if (n >= n_nodes) return;
    const float* W = Ws[half];
    const u64* bb = (const u64*)bs[half];

    u64 a[16];
#pragma unroll
    for (int jp = 0; jp < 16; jp++) a[jp] = bb[jp];

    const float4* x4 = (const float4*)x + (size_t)n * 16;
    for (int kc = 0; kc < 16; kc++) {
        float4 xv = x4[kc];
        const float* xa = (const float*)&xv;
#pragma unroll
        for (int e = 0; e < 4; e++)
            fma_row32(a, W + (kc * 4 + e) * 32, dup2(xa[e]));
    }

    float inv = 1.0f / fmaxf(half ? g_cntn[n] : g_cntp[n], 1.0f);
    const uint4* acc4 = (const uint4*)(half ? g_accNh : g_accPh) + (size_t)n * 4;
    uint4* xd = (uint4*)g_xpnh + (size_t)n * 8 + 4 * half;
#pragma unroll
    for (int q = 0; q < 4; q++) {
        float av[8];
        h8tof(acc4[q], av);
        float r[8];
#pragma unroll
        for (int j = 0; j < 4; j++) {
            float2 t = unpack2(a[4 * q + j]);
            r[2 * j]     = tanhf(t.x + av[2 * j] * inv);
            r[2 * j + 1] = tanhf(t.y + av[2 * j + 1] * inv);
        }
        uint4 u;
        u.x = pack_h2(r[0], r[1]); u.y = pack_h2(r[2], r[3]);
        u.z = pack_h2(r[4], r[5]); u.w = pack_h2(r[6], r[7]);
        xd[q] = u;
    }
}

// --------------------------- layer-2 aggregation ----------------------------
// 2 edges per thread; 8 chunk-threads per edge pair.
__global__ void k_edge2(int E, long total) {
    long idx = (long)blockIdx.x * blockDim.x + threadIdx.x;
    if (idx >= total) return;
    int p = (int)(idx >> 3);
    int c = (int)(idx & 7);
    int e0 = 2 * p;
    int4 es = __ldg((const int4*)g_es + p);
    bool has1 = (e0 + 1 < E);

    int s0 = es.x, d0 = es.y;
    int s1 = es.z, d1 = es.w;

    uint4 v0 = *((const uint4*)g_xpnh + (size_t)s0 * 8 + c);
    uint4 v1;
    if (has1) v1 = *((const uint4*)g_xpnh + (size_t)s1 * 8 + c);

    if (d0 >= 0) {
        red_v4h(g_accP2h + (size_t)d0 * 64 + c * 8, v0);
    } else {
        red_v4h(g_accN2h + (size_t)(~d0) * 64 + (((c + 4) & 7)) * 8, v0);
    }
    if (has1) {
        if (d1 >= 0) {
            red_v4h(g_accP2h + (size_t)d1 * 64 + c * 8, v1);
        } else {
            red_v4h(g_accN2h + (size_t)(~d1) * 64 + (((c + 4) & 7)) * 8, v1);
        }
    }
}

// ------------- node layer 2 + MLP head (pair-split, 2 threads/node) ---------
__global__ void __launch_bounds__(256)
k_node2(const float* __restrict__ Wp2, const float* __restrict__ bp2,
        const float* __restrict__ Wn2, const float* __restrict__ bn2,
        const float* __restrict__ Ww,  const float* __restrict__ bw,
        const float* __restrict__ Wm1, const float* __restrict__ bm1,
        const float* __restrict__ g1,  const float* __restrict__ be1,
        const float* __restrict__ rm1, const float* __restrict__ rv1,
        const float* __restrict__ Wm2, const float* __restrict__ bm2,
        const float* __restrict__ g2,  const float* __restrict__ be2,
        const float* __restrict__ rm2, const float* __restrict__ rv2,
        const float* __restrict__ Wm3, const float* __restrict__ bm3,
        float* __restrict__ outz, float* __restrict__ outp, int n_nodes) {
    extern __shared__ __align__(16) float sm[];
    float* Wps  = sm;                  // 96*32
    float* Wns  = Wps + 96 * 32;       // 96*32
    float* Wws  = Wns + 96 * 32;       // 64*64
    float* W1s  = Wws + 64 * 64;       // 64*64
    float* W2s  = W1s + 64 * 64;       // 64*64
    float* bps  = W2s + 64 * 64;       // 32
    float* bns  = bps + 32;            // 32
    float* bws  = bns + 32;            // 64
    float* sc1  = bws + 64;            // 64
    float* of1  = sc1 + 64;            // 64
    float* sc2  = of1 + 64;            // 64
    float* of2  = sc2 + 64;            // 64
    float* w3s  = of2 + 64;            // 64
    float* b3s  = w3s + 64;            // 4 (pad)

    int tid = threadIdx.x;
    for (int i = tid; i < 96 * 32; i += blockDim.x) { Wps[i] = Wp2[i]; Wns[i] = Wn2[i]; }
    for (int i = tid; i < 64 * 64; i += blockDim.x) {
        Wws[i] = Ww[i]; W1s[i] = Wm1[i]; W2s[i] = Wm2[i];
    }
    if (tid < 32) { bps[tid] = bp2[tid]; bns[tid] = bn2[tid]; }
    if (tid < 64) {
        bws[tid] = bw[tid];
        float s1 = g1[tid] * rsqrtf(rv1[tid] + 1e-5f);
        sc1[tid] = s1;
        of1[tid] = (bm1[tid] - rm1[tid]) * s1 + be1[tid];
        float s2 = g2[tid] * rsqrtf(rv2[tid] + 1e-5f);
        sc2[tid] = s2;
        of2[tid] = (bm2[tid] - rm2[tid]) * s2 + be2[tid];
        w3s[tid] = Wm3[tid];
    }
    if (tid == 0) b3s[0] = bm3[0];
    __syncthreads();

    long gidx = (long)blockIdx.x * blockDim.x + tid;
    int n = (int)(gidx >> 1);
    int half = (int)(gidx & 1);
    bool valid = (n < n_nodes);
    int nc = valid ? n : (n_nodes - 1);
    int co = 32 * half;  // this thread's output-column offset

    float invp = 1.0f / fmaxf(g_cntp[nc], 1.0f);
    float invn = 1.0f / fmaxf(g_cntn[nc], 1.0f);

    // ---- loop 1: this half's 32-wide hidden (hp for half0, hn for half1) ----
    u64 acc[16];
    {
        const float* Wl = half ? Wns : Wps;
        const u64* bb = (const u64*)(half ? bns : bps);
#pragma unroll
        for (int jp = 0; jp < 16; jp++) acc[jp] = bb[jp];

        const uint4* aP4 = (const uint4*)g_accP2h + (size_t)nc * 8 + 4 * half;
        const uint4* aN4 = (const uint4*)g_accN2h + (size_t)nc * 8 + 4 * half;
        const uint4* xx4 = (const uint4*)g_xpnh   + (size_t)nc * 8 + 4 * half;
        for (int kc = 0; kc < 4; kc++) {
            float Aa[8], Ba[8], Pa[8];
            h8tof(aP4[kc], Aa);   // pos-mean operand (A or C)
            h8tof(aN4[kc], Ba);   // neg-mean operand (B or D)
            h8tof(xx4[kc], Pa);   // self (xp or xn)
#pragma unroll
            for (int e = 0; e < 8; e++) {
                int k = kc * 8 + e;
                fma_row32(acc, Wl + k * 32,        dup2(Aa[e] * invp));
                fma_row32(acc, Wl + (32 + k) * 32, dup2(Ba[e] * invn));
                fma_row32(acc, Wl + (64 + k) * 32, dup2(Pa[e]));
            }
        }
    }
    float mine[32];
#pragma unroll
    for (int jp = 0; jp < 16; jp++) {
        float2 t = unpack2(acc[jp]);
        mine[2 * jp] = tanhf(t.x);
        mine[2 * jp + 1] = tanhf(t.y);
    }

    // ---- loop 2: z-half = tanh( z2 @ Ww[:, co:co+32] + bw ) ----
    {
        const u64* bwp = (const u64*)(bws + co);
#pragma unroll
        for (int jp = 0; jp < 16; jp++) acc[jp] = bwp[jp];
#pragma unroll
        for (int j = 0; j < 32; j++)   // own half of inputs
            fma_row32(acc, Wws + (co + j) * 64 + co, dup2(mine[j]));
#pragma unroll
        for (int j = 0; j < 32; j++) { // partner half via shfl
            float v = __shfl_xor_sync(0xffffffffu, mine[j], 1);
            fma_row32(acc, Wws + ((32 - co) + j) * 64 + co, dup2(v));
        }
#pragma unroll
        for (int jp = 0; jp < 16; jp++) {
            float2 t = unpack2(acc[jp]);
            mine[2 * jp] = tanhf(t.x);
            mine[2 * jp + 1] = tanhf(t.y);
        }
    }
    // store z-half
    if (valid) {
        float4* zd = (float4*)(outz + (size_t)n * 64 + co);
#pragma unroll
        for (int q = 0; q < 8; q++)
            zd[q] = make_float4(mine[4 * q], mine[4 * q + 1],
                                mine[4 * q + 2], mine[4 * q + 3]);
    }

    // ---- loop 3: h-half = relu(bn1(z @ Wm1[:, co:co+32])) ----
    {
#pragma unroll
        for (int jp = 0; jp < 16; jp++) acc[jp] = 0ull;
#pragma unroll
        for (int j = 0; j < 32; j++)
            fma_row32(acc, W1s + (co + j) * 64 + co, dup2(mine[j]));
#pragma unroll
        for (int j = 0; j < 32; j++) {
            float v = __shfl_xor_sync(0xffffffffu, mine[j], 1);
            fma_row32(acc, W1s + ((32 - co) + j) * 64 + co, dup2(v));
        }
#pragma unroll
        for (int jp = 0; jp < 16; jp++) {
            float2 t = unpack2(acc[jp]);
            mine[2 * jp]     = fmaxf(t.x * sc1[co + 2 * jp]     + of1[co + 2 * jp],     0.f);
            mine[2 * jp + 1] = fmaxf(t.y * sc1[co + 2 * jp + 1] + of1[co + 2 * jp + 1], 0.f);
        }
    }
    // ---- loop 4: r-half = relu(bn2(h @ Wm2[:, co:co+32])); dot w3 ----
    {
#pragma unroll
        for (int jp = 0; jp < 16; jp++) acc[jp] = 0ull;
#pragma unroll
        for (int j = 0; j < 32; j++)
            fma_row32(acc, W2s + (co + j) * 64 + co, dup2(mine[j]));
#pragma unroll
        for (int j = 0; j < 32; j++) {
            float v = __shfl_xor_sync(0xffffffffu, mine[j], 1);
            fma_row32(acc, W2s + ((32 - co) + j) * 64 + co, dup2(v));
        }
        float part = 0.f;
#pragma unroll
        for (int jp = 0; jp < 16; jp++) {
            float2 t = unpack2(acc[jp]);
            float r0 = fmaxf(t.x * sc2[co + 2 * jp]     + of2[co + 2 * jp],     0.f);
            float r1 = fmaxf(t.y * sc2[co + 2 * jp + 1] + of2[co + 2 * jp + 1], 0.f);
            part += r0 * w3s[co + 2 * jp] + r1 * w3s[co + 2 * jp + 1];
        }
        part += __shfl_xor_sync(0xffffffffu, part, 1);
        if (valid && half == 0)
            outp[n] = 1.0f / (1.0f + expf(-(part + b3s[0])));
    }
}

// -------------------------------- launcher ----------------------------------
extern "C" void kernel_launch(void* const* d_in, const int* in_sizes, int n_in,
                              void* d_out, int out_size) {
    const float* x   = (const float*)d_in[0];
    const int*   ei  = (const int*)d_in[1];
    const float* Wp1 = (const float*)d_in[2];
    const float* bp1 = (const float*)d_in[3];
    const float* Wn1 = (const float*)d_in[4];
    const float* bn1 = (const float*)d_in[5];
    const float* Wp2 = (const float*)d_in[6];
    const float* bp2 = (const float*)d_in[7];
    const float* Wn2 = (const float*)d_in[8];
    const float* bn2 = (const float*)d_in[9];
    const float* Ww  = (const float*)d_in[10];
    const float* bw  = (const float*)d_in[11];
    const float* Wm1 = (const float*)d_in[12];
    const float* bm1 = (const float*)d_in[13];
    const float* g1  = (const float*)d_in[14];
    const float* be1 = (const float*)d_in[15];
    const float* rm1 = (const float*)d_in[16];
    const float* rv1 = (const float*)d_in[17];
    const float* Wm2 = (const float*)d_in[18];
    const float* bm2 = (const float*)d_in[19];
    const float* g2  = (const float*)d_in[20];
    const float* be2 = (const float*)d_in[21];
    const float* rm2 = (const float*)d_in[22];
    const float* rv2 = (const float*)d_in[23];
    const float* Wm3 = (const float*)d_in[24];
    const float* bm3 = (const float*)d_in[25];

    int  Nn = in_sizes[0] / DD;
    int  E  = in_sizes[1] / 3;

    float* out  = (float*)d_out;
    float* outz = out;
    float* outp = out + (size_t)Nn * DD;

    const int NODE2_SMEM = (96 * 32 * 2 + 64 * 64 * 3 + 32 * 2 + 64 * 6 + 4) * 4;
    cudaFuncSetAttribute(k_node2, cudaFuncAttributeMaxDynamicSharedMemorySize,
                         NODE2_SMEM);

    k_init<<<2048, 256>>>(ei, E, Nn);

    long tp = (long)Nn * 2;
    k_proj1<<<(int)((tp + 255) / 256), 256>>>(x, Wp1, Wn1, Nn);

    int npairs = (E + 1) / 2;
    long t1 = (long)npairs * 4;
    k_edge1<<<(int)((t1 + 255) / 256), 256>>>(E, t1);

    k_node1<<<(int)((tp + 255) / 256), 256>>>(x, Wp1, bp1, Wn1, bn1, Nn);

    long t2 = (long)npairs * 8;
    k_edge2<<<(int)((t2 + 255) / 256), 256>>>(E, t2);

    k_node2<<<(int)((tp + 255) / 256), 256, NODE2_SMEM>>>(
        Wp2, bp2, Wn2, bn2, Ww, bw,
        Wm1, bm1, g1, be1, rm1, rv1,
        Wm2, bm2, g2, be2, rm2, rv2,
        Wm3, bm3, outz, outp, Nn);
}

// round 7
// speedup vs baseline: 2.3329x; 2.3329x over previous
#include <cuda_runtime.h>
#include <cuda_fp16.h>
#include <math.h>

#define NMAX 100000
#define EMAX 1310720
#define DD 64

// -------- persistent scratch (device globals; no allocation allowed) --------
__device__ __align__(16) __half g_xh[NMAX * 64];     // x in fp16
__device__ __align__(16) __half g_Ph[NMAX * 32];     // x @ Wp1[:64]
__device__ __align__(16) __half g_Qh[NMAX * 32];     // x @ Wn1[:64]
__device__ __align__(16) __half g_RSh[NMAX * 64];    // [x@Wp1[64:]+bp1 | x@Wn1[64:]+bn1]
__device__ __align__(16) __half g_accPh[NMAX * 32];
__device__ __align__(16) __half g_accNh[NMAX * 32];
__device__ __align__(16) __half g_xpnh[NMAX * 64];   // [xp | xn]
__device__ __align__(16) __half g_accP2h[NMAX * 64]; // pos: [sum xp | sum xn] = [A|C]
__device__ __align__(16) __half g_accN2h[NMAX * 64]; // neg: [sum xn | sum xp] = [B|D]
__device__ __align__(16) float  g_cntp[NMAX];
__device__ __align__(16) float  g_cntn[NMAX];
__device__ __align__(16) int2   g_es[EMAX];          // {src, dst or ~dst(neg)}

// ------------------------------ tiny helpers --------------------------------
__device__ __forceinline__ void red_v4h(__half* p, uint4 v) {
    asm volatile("red.global.add.noftz.v4.f16x2 [%0], {%1,%2,%3,%4};"
                 :: "l"(p), "r"(v.x), "r"(v.y), "r"(v.z), "r"(v.w)
                 : "memory");
}
__device__ __forceinline__ unsigned packh2(float a, float b) {
    __half2 h = __floats2half2_rn(a, b);
    return *(unsigned*)&h;
}
__device__ __forceinline__ void h8tof(uint4 v, float* o) {
    const __half2* h = (const __half2*)&v;
#pragma unroll
    for (int j = 0; j < 4; j++) {
        float2 f = __half22float2(h[j]);
        o[2 * j] = f.x;
        o[2 * j + 1] = f.y;
    }
}
__device__ __forceinline__ uint4 scale8(uint4 v, __half2 s) {
    __half2* h = (__half2*)&v;
    h[0] = __hmul2(h[0], s); h[1] = __hmul2(h[1], s);
    h[2] = __hmul2(h[2], s); h[3] = __hmul2(h[3], s);
    return v;
}

// ---------------- mma.m16n8k16 f16 -> f32, analytic fragments ---------------
__device__ __forceinline__ void mma16816(float* c, const unsigned* a, const unsigned* b) {
    asm volatile(
        "mma.sync.aligned.m16n8k16.row.col.f32.f16.f16.f32 "
        "{%0,%1,%2,%3}, {%4,%5,%6,%7}, {%8,%9}, {%0,%1,%2,%3};"
        : "+f"(c[0]), "+f"(c[1]), "+f"(c[2]), "+f"(c[3])
        : "r"(a[0]), "r"(a[1]), "r"(a[2]), "r"(a[3]), "r"(b[0]), "r"(b[1]));
}
// A row-major [16 x K] in smem, stride in halves (even), k0 multiple of 16
__device__ __forceinline__ void lda(unsigned* a, const __half* base, int stride,
                                    int k0, int lane) {
    int gr = lane >> 2, gc = lane & 3;
    const __half* p = base + gr * stride + k0 + 2 * gc;
    a[0] = *(const unsigned*)p;
    a[1] = *(const unsigned*)(p + 8 * stride);
    a[2] = *(const unsigned*)(p + 8);
    a[3] = *(const unsigned*)(p + 8 * stride + 8);
}
// B as WT[n][k] row-major (= B col-major), stride in halves
__device__ __forceinline__ void ldb(unsigned* b, const __half* WT, int stride,
                                    int n0, int k0, int lane) {
    int gn = lane >> 2, gc = lane & 3;
    const __half* p = WT + (n0 + gn) * stride + k0 + 2 * gc;
    b[0] = *(const unsigned*)p;
    b[1] = *(const unsigned*)(p + 8);
}

// ------------------- init: pack edges + zero accs + x->fp16 -----------------
__global__ void k_init(const int* __restrict__ ei, const float* __restrict__ x,
                       int E, int n) {
    int i = blockIdx.x * blockDim.x + threadIdx.x;
    int stride = gridDim.x * blockDim.x;
    for (int e = i; e < E; e += stride) {
        long eb = 3L * e;
        int s  = __ldg(ei + eb);
        int d  = __ldg(ei + eb + 1);
        int sg = __ldg(ei + eb + 2);
        g_es[e] = make_int2(s, (sg > 0) ? d : ~d);
    }
    uint4 z4 = make_uint4(0u, 0u, 0u, 0u);
    int nh = n * 4;
    for (int j = i; j < nh; j += stride) {
        ((uint4*)g_accPh)[j] = z4;
        ((uint4*)g_accNh)[j] = z4;
    }
    int nd = n * 8;
    for (int j = i; j < nd; j += stride) {
        ((uint4*)g_accP2h)[j] = z4;
        ((uint4*)g_accN2h)[j] = z4;
    }
    int nc = n / 4;
    for (int j = i; j < nc; j += stride) {
        ((uint4*)g_cntp)[j] = z4;
        ((uint4*)g_cntn)[j] = z4;
    }
    const float4* x4 = (const float4*)x;
    for (int j = i; j < nd; j += stride) {
        float4 f0 = x4[2 * j], f1 = x4[2 * j + 1];
        uint4 u;
        u.x = packh2(f0.x, f0.y); u.y = packh2(f0.z, f0.w);
        u.z = packh2(f1.x, f1.y); u.w = packh2(f1.z, f1.w);
        ((uint4*)g_xh)[j] = u;
    }
}

// ----------- projection GEMM (tensor cores): [N x 64] @ [64 x 128] ----------
// cols 0..31 -> P, 32..63 -> Q, 64..95 -> R(+bp1), 96..127 -> S(+bn1)
__global__ void __launch_bounds__(256)
k_projTC(const float* __restrict__ Wp1, const float* __restrict__ bp1,
         const float* __restrict__ Wn1, const float* __restrict__ bn1,
         int n_nodes, int n_tiles) {
    __shared__ __align__(16) __half WT[128 * 72];
    __shared__ float b1s[64];
    int tid = threadIdx.x;
    for (int i = tid; i < 64 * 128; i += 256) {
        int k = i >> 7, col = i & 127;
        float w;
        if (col < 32)       w = Wp1[k * 32 + col];
        else if (col < 64)  w = Wn1[k * 32 + (col - 32)];
        else if (col < 96)  w = Wp1[(64 + k) * 32 + (col - 64)];
        else                w = Wn1[(64 + k) * 32 + (col - 96)];
        WT[col * 72 + k] = __float2half(w);
    }
    if (tid < 32) { b1s[tid] = bp1[tid]; b1s[32 + tid] = bn1[tid]; }
    __syncthreads();

    int wid = tid >> 5, lane = tid & 31;
    int tile = blockIdx.x * 8 + wid;
    if (tile >= n_tiles) return;
    int base = tile * 16;
    int gr = lane >> 2, gc = lane & 3;
    int r0 = base + gr, r1 = base + gr + 8;
    bool v0 = r0 < n_nodes, v1 = r1 < n_nodes;
    size_t rr0 = v0 ? (size_t)r0 : 0, rr1 = v1 ? (size_t)r1 : 0;

    float c[16][4];
#pragma unroll
    for (int t = 0; t < 16; t++)
        c[t][0] = c[t][1] = c[t][2] = c[t][3] = 0.f;

    for (int kc = 0; kc < 4; kc++) {
        unsigned a[4];
        const __half* p0 = g_xh + rr0 * 64 + 16 * kc + 2 * gc;
        const __half* p1 = g_xh + rr1 * 64 + 16 * kc + 2 * gc;
        a[0] = *(const unsigned*)p0;
        a[1] = *(const unsigned*)p1;
        a[2] = *(const unsigned*)(p0 + 8);
        a[3] = *(const unsigned*)(p1 + 8);
#pragma unroll
        for (int t = 0; t < 16; t++) {
            unsigned b[2];
            ldb(b, WT, 72, 8 * t, 16 * kc, lane);
            mma16816(c[t], a, b);
        }
    }
#pragma unroll
    for (int t = 0; t < 16; t++) {
        int colw = 8 * t + 2 * gc;
        if (colw < 64) {
            __half* dstb = (colw < 32) ? g_Ph : g_Qh;
            int cw = colw & 31;
            if (v0) *(unsigned*)(dstb + rr0 * 32 + cw) = packh2(c[t][0], c[t][1]);
            if (v1) *(unsigned*)(dstb + rr1 * 32 + cw) = packh2(c[t][2], c[t][3]);
        } else {
            float bb0 = b1s[colw - 64], bb1 = b1s[colw - 63];
            if (v0) *(unsigned*)(g_RSh + rr0 * 64 + (colw - 64)) =
                packh2(c[t][0] + bb0, c[t][1] + bb1);
            if (v1) *(unsigned*)(g_RSh + rr1 * 64 + (colw - 64)) =
                packh2(c[t][2] + bb0, c[t][3] + bb1);
        }
    }
}

// --------------------------- layer-1 aggregation ----------------------------
__global__ void k_edge1(long total) {
    long idx = (long)blockIdx.x * blockDim.x + threadIdx.x;
    if (idx >= total) return;
    int e = (int)(idx >> 2);
    int c = (int)(idx & 3);
    int2 sd = __ldg(&g_es[e]);
    int s = sd.x, d = sd.y;
    bool pos = (d >= 0);
    if (!pos) d = ~d;
    uint4 v = *((const uint4*)(pos ? g_Ph : g_Qh) + (size_t)s * 4 + c);
    red_v4h((pos ? g_accPh : g_accNh) + (size_t)d * 32 + c * 8, v);
    if (c == 0) atomicAdd(pos ? (g_cntp + d) : (g_cntn + d), 1.0f);
}

// --------------------- node layer 1: elementwise tanh -----------------------
__global__ void k_node1e(long total) {
    long idx = (long)blockIdx.x * blockDim.x + threadIdx.x;
    if (idx >= total) return;
    int n = (int)(idx >> 3);
    int c = (int)(idx & 7);
    uint4 rs = ((const uint4*)g_RSh)[idx];
    uint4 acc;
    float inv;
    if (c < 4) {
        acc = ((const uint4*)g_accPh)[(size_t)n * 4 + c];
        inv = 1.0f / fmaxf(g_cntp[n], 1.0f);
    } else {
        acc = ((const uint4*)g_accNh)[(size_t)n * 4 + (c - 4)];
        inv = 1.0f / fmaxf(g_cntn[n], 1.0f);
    }
    float rf[8], af[8];
    h8tof(rs, rf);
    h8tof(acc, af);
    uint4 o;
    unsigned* ou = (unsigned*)&o;
#pragma unroll
    for (int j = 0; j < 4; j++)
        ou[j] = packh2(tanhf(rf[2 * j] + af[2 * j] * inv),
                       tanhf(rf[2 * j + 1] + af[2 * j + 1] * inv));
    ((uint4*)g_xpnh)[idx] = o;
}

// --------------------------- layer-2 aggregation ----------------------------
__global__ void k_edge2(long total) {
    long idx = (long)blockIdx.x * blockDim.x + threadIdx.x;
    if (idx >= total) return;
    int e = (int)(idx >> 3);
    int c = (int)(idx & 7);
    int2 sd = __ldg(&g_es[e]);
    int s = sd.x, d = sd.y;
    uint4 v = *((const uint4*)g_xpnh + (size_t)s * 8 + c);
    if (d >= 0) {
        red_v4h(g_accP2h + (size_t)d * 64 + c * 8, v);
    } else {
        red_v4h(g_accN2h + (size_t)(~d) * 64 + (((c + 4) & 7)) * 8, v);
    }
}

// ------------- node layer 2 + MLP head: tensor-core warp tiles --------------
// per warp: 16 nodes. loop1: hp=[A,B,xp]@Wp2 (K=96,N=32), hn=[C,D,xn]@Wn2.
// loop2: z=tanh(z2@Ww+bw)  loop3: h=relu(bn1(z@Wm1))  loop4: r=relu(bn2(h@Wm2)),
// prob=sigmoid(r.w3+b3).
__global__ void __launch_bounds__(256)
k_node2TC(const float* __restrict__ Wp2, const float* __restrict__ bp2,
          const float* __restrict__ Wn2, const float* __restrict__ bn2,
          const float* __restrict__ Ww,  const float* __restrict__ bw,
          const float* __restrict__ Wm1, const float* __restrict__ bm1,
          const float* __restrict__ g1,  const float* __restrict__ be1,
          const float* __restrict__ rm1, const float* __restrict__ rv1,
          const float* __restrict__ Wm2, const float* __restrict__ bm2,
          const float* __restrict__ g2,  const float* __restrict__ be2,
          const float* __restrict__ rm2, const float* __restrict__ rv2,
          const float* __restrict__ Wm3, const float* __restrict__ bm3,
          float* __restrict__ outz, float* __restrict__ outp,
          int n_nodes, int n_tiles) {
    extern __shared__ __align__(16) __half smh[];
    __half* WpT = smh;                    // 32 x 104
    __half* WnT = smh + 3328;             // 32 x 104
    __half* WwT = smh + 6656;             // 64 x 72
    __half* W1T = smh + 11264;            // 64 x 72
    __half* W2T = smh + 15872;            // 64 x 72
    // per-warp buffers
    float* fb = (float*)(smh + 56320);
    float* bp2s = fb;         // 32
    float* bn2s = fb + 32;    // 32
    float* bws  = fb + 64;    // 64
    float* sc1  = fb + 128;   // 64
    float* of1  = fb + 192;   // 64
    float* sc2  = fb + 256;   // 64
    float* of2  = fb + 320;   // 64
    float* w3s  = fb + 384;   // 64
    // fb[448] = b3

    int tid = threadIdx.x;
    for (int i = tid; i < 96 * 32; i += 256) {
        int k = i >> 5, nn = i & 31;
        WpT[nn * 104 + k] = __float2half(Wp2[i]);
        WnT[nn * 104 + k] = __float2half(Wn2[i]);
    }
    for (int i = tid; i < 64 * 64; i += 256) {
        int k = i >> 6, nn = i & 63;
        WwT[nn * 72 + k] = __float2half(Ww[i]);
        W1T[nn * 72 + k] = __float2half(Wm1[i]);
        W2T[nn * 72 + k] = __float2half(Wm2[i]);
    }
    if (tid < 32) { bp2s[tid] = bp2[tid]; bn2s[tid] = bn2[tid]; }
    if (tid < 64) {
        bws[tid] = bw[tid];
        float s1 = g1[tid] * rsqrtf(rv1[tid] + 1e-5f);
        sc1[tid] = s1;
        of1[tid] = (bm1[tid] - rm1[tid]) * s1 + be1[tid];
        float s2 = g2[tid] * rsqrtf(rv2[tid] + 1e-5f);
        sc2[tid] = s2;
        of2[tid] = (bm2[tid] - rm2[tid]) * s2 + be2[tid];
        w3s[tid] = Wm3[tid];
    }
    if (tid == 0) fb[448] = bm3[0];
    __syncthreads();

    int wid = tid >> 5, lane = tid & 31;
    __half* Ahp = smh + 20480 + wid * 1664;  // 16 x 104
    __half* Ahn = smh + 33792 + wid * 1664;  // 16 x 104
    __half* zs  = smh + 47104 + wid * 1152;  // 16 x 72

    int tile = blockIdx.x * 8 + wid;
    if (tile >= n_tiles) return;
    int base = tile * 16;
    int gr = lane >> 2, gc = lane & 3;

    // ---- stage scaled inputs: Ahp = [A*ivp | B*ivn | xp], Ahn = [C*ivp | D*ivn | xn]
    {
        int row = lane >> 1, part = lane & 1;
        int n = base + row;
        if (n >= n_nodes) n = n_nodes - 1;
        __half2 ivp = __float2half2_rn(1.0f / fmaxf(g_cntp[n], 1.0f));
        __half2 ivn = __float2half2_rn(1.0f / fmaxf(g_cntn[n], 1.0f));
        const uint4* sp = (const uint4*)g_accP2h + (size_t)n * 8;
        const uint4* sn = (const uint4*)g_accN2h + (size_t)n * 8;
        const uint4* sx = (const uint4*)g_xpnh + (size_t)n * 8;
        uint4* rp = (uint4*)(Ahp + row * 104);
        uint4* rn = (uint4*)(Ahn + row * 104);
        if (part == 0) {
#pragma unroll
            for (int j = 0; j < 4; j++) {
                rp[j] = scale8(sp[j], ivp);       // A
                rn[j] = scale8(sp[4 + j], ivp);   // C
            }
            rp[4] = scale8(sn[0], ivn); rp[5] = scale8(sn[1], ivn);  // B lo
            rn[4] = scale8(sn[4], ivn); rn[5] = scale8(sn[5], ivn);  // D lo
        } else {
            rp[6] = scale8(sn[2], ivn); rp[7] = scale8(sn[3], ivn);  // B hi
            rn[6] = scale8(sn[6], ivn); rn[7] = scale8(sn[7], ivn);  // D hi
#pragma unroll
            for (int j = 0; j < 4; j++) {
                rp[8 + j] = sx[j];        // xp
                rn[8 + j] = sx[4 + j];    // xn
            }
        }
    }
    __syncwarp();

    // ---- loop1: hp (t 0..3 via WpT), hn (t 4..7 via WnT), K = 96 ----
    float c1[8][4];
#pragma unroll
    for (int t = 0; t < 8; t++)
        c1[t][0] = c1[t][1] = c1[t][2] = c1[t][3] = 0.f;
    for (int kc = 0; kc < 6; kc++) {
        unsigned a[4], b[2];
        lda(a, Ahp, 104, 16 * kc, lane);
#pragma unroll
        for (int t = 0; t < 4; t++) {
            ldb(b, WpT, 104, 8 * t, 16 * kc, lane);
            mma16816(c1[t], a, b);
        }
        lda(a, Ahn, 104, 16 * kc, lane);
#pragma unroll
        for (int t = 0; t < 4; t++) {
            ldb(b, WnT, 104, 8 * t, 16 * kc, lane);
            mma16816(c1[4 + t], a, b);
        }
    }
    __syncwarp();
#pragma unroll
    for (int t = 0; t < 8; t++) {
        int c32 = 8 * (t & 3) + 2 * gc;
        const float* barr = (t < 4) ? bp2s : bn2s;
        float b0 = barr[c32], b1 = barr[c32 + 1];
        int cz = (t < 4) ? c32 : 32 + c32;
        *(unsigned*)(zs + gr * 72 + cz) =
            packh2(tanhf(c1[t][0] + b0), tanhf(c1[t][1] + b1));
        *(unsigned*)(zs + (gr + 8) * 72 + cz) =
            packh2(tanhf(c1[t][2] + b0), tanhf(c1[t][3] + b1));
    }
    __syncwarp();

    int nr0 = base + gr, nr1 = base + gr + 8;
    bool v0 = nr0 < n_nodes, v1 = nr1 < n_nodes;

    // ---- loop2: z = tanh(z2 @ Ww + bw), K=64, N=64 ----
    float c2[8][4];
#pragma unroll
    for (int t = 0; t < 8; t++)
        c2[t][0] = c2[t][1] = c2[t][2] = c2[t][3] = 0.f;
    for (int kc = 0; kc < 4; kc++) {
        unsigned a[4], b[2];
        lda(a, zs, 72, 16 * kc, lane);
#pragma unroll
        for (int t = 0; t < 8; t++) {
            ldb(b, WwT, 72, 8 * t, 16 * kc, lane);
            mma16816(c2[t], a, b);
        }
    }
    __syncwarp();
#pragma unroll
    for (int t = 0; t < 8; t++) {
        int col = 8 * t + 2 * gc;
        float z0 = tanhf(c2[t][0] + bws[col]);
        float z1 = tanhf(c2[t][1] + bws[col + 1]);
        float z2v = tanhf(c2[t][2] + bws[col]);
        float z3 = tanhf(c2[t][3] + bws[col + 1]);
        if (v0) *(float2*)(outz + (size_t)nr0 * 64 + col) = make_float2(z0, z1);
        if (v1) *(float2*)(outz + (size_t)nr1 * 64 + col) = make_float2(z2v, z3);
        *(unsigned*)(zs + gr * 72 + col) = packh2(z0, z1);
        *(unsigned*)(zs + (gr + 8) * 72 + col) = packh2(z2v, z3);
    }
    __syncwarp();

    // ---- loop3: h = relu(bn1(z @ Wm1)) ----
#pragma unroll
    for (int t = 0; t < 8; t++)
        c2[t][0] = c2[t][1] = c2[t][2] = c2[t][3] = 0.f;
    for (int kc = 0; kc < 4; kc++) {
        unsigned a[4], b[2];
        lda(a, zs, 72, 16 * kc, lane);
#pragma unroll
        for (int t = 0; t < 8; t++) {
            ldb(b, W1T, 72, 8 * t, 16 * kc, lane);
            mma16816(c2[t], a, b);
        }
    }
    __syncwarp();
#pragma unroll
    for (int t = 0; t < 8; t++) {
        int col = 8 * t + 2 * gc;
        float h0 = fmaxf(c2[t][0] * sc1[col] + of1[col], 0.f);
        float h1 = fmaxf(c2[t][1] * sc1[col + 1] + of1[col + 1], 0.f);
        float h2 = fmaxf(c2[t][2] * sc1[col] + of1[col], 0.f);
        float h3 = fmaxf(c2[t][3] * sc1[col + 1] + of1[col + 1], 0.f);
        *(unsigned*)(zs + gr * 72 + col) = packh2(h0, h1);
        *(unsigned*)(zs + (gr + 8) * 72 + col) = packh2(h2, h3);
    }
    __syncwarp();

    // ---- loop4: r = relu(bn2(h @ Wm2)); prob = sigmoid(r.w3 + b3) ----
#pragma unroll
    for (int t = 0; t < 8; t++)
        c2[t][0] = c2[t][1] = c2[t][2] = c2[t][3] = 0.f;
    for (int kc = 0; kc < 4; kc++) {
        unsigned a[4], b[2];
        lda(a, zs, 72, 16 * kc, lane);
#pragma unroll
        for (int t = 0; t < 8; t++) {
            ldb(b, W2T, 72, 8 * t, 16 * kc, lane);
            mma16816(c2[t], a, b);
        }
    }
    float p0 = 0.f, p1 = 0.f;
#pragma unroll
    for (int t = 0; t < 8; t++) {
        int col = 8 * t + 2 * gc;
        float r0 = fmaxf(c2[t][0] * sc2[col] + of2[col], 0.f);
        float r1 = fmaxf(c2[t][1] * sc2[col + 1] + of2[col + 1], 0.f);
        float r2 = fmaxf(c2[t][2] * sc2[col] + of2[col], 0.f);
        float r3 = fmaxf(c2[t][3] * sc2[col + 1] + of2[col + 1], 0.f);
        p0 += r0 * w3s[col] + r1 * w3s[col + 1];
        p1 += r2 * w3s[col] + r3 * w3s[col + 1];
    }
    p0 += __shfl_xor_sync(0xffffffffu, p0, 1);
    p0 += __shfl_xor_sync(0xffffffffu, p0, 2);
    p1 += __shfl_xor_sync(0xffffffffu, p1, 1);
    p1 += __shfl_xor_sync(0xffffffffu, p1, 2);
    if ((lane & 3) == 0) {
        float b3 = fb[448];
        if (v0) outp[nr0] = 1.0f / (1.0f + expf(-(p0 + b3)));
        if (v1) outp[nr1] = 1.0f / (1.0f + expf(-(p1 + b3)));
    }
}

// -------------------------------- launcher ----------------------------------
extern "C" void kernel_launch(void* const* d_in, const int* in_sizes, int n_in,
                              void* d_out, int out_size) {
    const float* x   = (const float*)d_in[0];
    const int*   ei  = (const int*)d_in[1];
    const float* Wp1 = (const float*)d_in[2];
    const float* bp1 = (const float*)d_in[3];
    const float* Wn1 = (const float*)d_in[4];
    const float* bn1 = (const float*)d_in[5];
    const float* Wp2 = (const float*)d_in[6];
    const float* bp2 = (const float*)d_in[7];
    const float* Wn2 = (const float*)d_in[8];
    const float* bn2 = (const float*)d_in[9];
    const float* Ww  = (const float*)d_in[10];
    const float* bw  = (const float*)d_in[11];
    const float* Wm1 = (const float*)d_in[12];
    const float* bm1 = (const float*)d_in[13];
    const float* g1  = (const float*)d_in[14];
    const float* be1 = (const float*)d_in[15];
    const float* rm1 = (const float*)d_in[16];
    const float* rv1 = (const float*)d_in[17];
    const float* Wm2 = (const float*)d_in[18];
    const float* bm2 = (const float*)d_in[19];
    const float* g2  = (const float*)d_in[20];
    const float* be2 = (const float*)d_in[21];
    const float* rm2 = (const float*)d_in[22];
    const float* rv2 = (const float*)d_in[23];
    const float* Wm3 = (const float*)d_in[24];
    const float* bm3 = (const float*)d_in[25];

    int Nn = in_sizes[0] / DD;
    int E  = in_sizes[1] / 3;

    float* out  = (float*)d_out;
    float* outz = out;
    float* outp = out + (size_t)Nn * DD;

    int n_tiles = (Nn + 15) / 16;
    int n_blks  = (n_tiles + 7) / 8;

    const int NODE2_SMEM = 56320 * 2 + 452 * 4;  // 114448 B
    cudaFuncSetAttribute(k_node2TC, cudaFuncAttributeMaxDynamicSharedMemorySize,
                         NODE2_SMEM);

    k_init<<<2048, 256>>>(ei, x, E, Nn);

    k_projTC<<<n_blks, 256>>>(Wp1, bp1, Wn1, bn1, Nn, n_tiles);

    long t1 = (long)E * 4;
    k_edge1<<<(int)((t1 + 255) / 256), 256>>>(t1);

    long tn = (long)Nn * 8;
    k_node1e<<<(int)((tn + 255) / 256), 256>>>(tn);

    long t2 = (long)E * 8;
    k_edge2<<<(int)((t2 + 255) / 256), 256>>>(t2);

    k_node2TC<<<n_blks, 256, NODE2_SMEM>>>(
        Wp2, bp2, Wn2, bn2, Ww, bw,
        Wm1, bm1, g1, be1, rm1, rv1,
        Wm2, bm2, g2, be2, rm2, rv2,
        Wm3, bm3, outz, outp, Nn, n_tiles);
}

// round 8
// speedup vs baseline: 2.4335x; 1.0431x over previous
#include <cuda_runtime.h>
#include <cuda_fp16.h>
#include <math.h>

#define NMAX 100000
#define EMAX 1310720
#define DD 64

// -------- persistent scratch (device globals; no allocation allowed) --------
__device__ __align__(16) __half g_Ph[NMAX * 32];     // x @ Wp1[:64]
__device__ __align__(16) __half g_Qh[NMAX * 32];     // x @ Wn1[:64]
__device__ __align__(16) __half g_RSh[NMAX * 64];    // [x@Wp1[64:]+bp1 | x@Wn1[64:]+bn1]
__device__ __align__(16) __half g_accPh[NMAX * 32];
__device__ __align__(16) __half g_accNh[NMAX * 32];
__device__ __align__(16) __half g_xpnh[NMAX * 64];   // [xp | xn]
__device__ __align__(16) __half g_accP2h[NMAX * 64]; // pos: [sum xp | sum xn] = [A|C]
__device__ __align__(16) __half g_accN2h[NMAX * 64]; // neg: [sum xn | sum xp] = [B|D]
__device__ __align__(16) float  g_cntp[NMAX];
__device__ __align__(16) float  g_cntn[NMAX];
__device__ __align__(16) int2   g_es[EMAX];          // {src, dst or ~dst(neg)}

// ------------------------------ tiny helpers --------------------------------
__device__ __forceinline__ void red_v4h(__half* p, uint4 v) {
    asm volatile("red.global.add.noftz.v4.f16x2 [%0], {%1,%2,%3,%4};"
                 :: "l"(p), "r"(v.x), "r"(v.y), "r"(v.z), "r"(v.w)
                 : "memory");
}
__device__ __forceinline__ unsigned packh2(float a, float b) {
    __half2 h = __floats2half2_rn(a, b);
    return *(unsigned*)&h;
}
__device__ __forceinline__ void h8tof(uint4 v, float* o) {
    const __half2* h = (const __half2*)&v;
#pragma unroll
    for (int j = 0; j < 4; j++) {
        float2 f = __half22float2(h[j]);
        o[2 * j] = f.x;
        o[2 * j + 1] = f.y;
    }
}
__device__ __forceinline__ uint4 scale8(uint4 v, __half2 s) {
    __half2* h = (__half2*)&v;
    h[0] = __hmul2(h[0], s); h[1] = __hmul2(h[1], s);
    h[2] = __hmul2(h[2], s); h[3] = __hmul2(h[3], s);
    return v;
}

// ---------------- mma.m16n8k16 f16 -> f32, analytic fragments ---------------
__device__ __forceinline__ void mma16816(float* c, const unsigned* a, const unsigned* b) {
    asm volatile(
        "mma.sync.aligned.m16n8k16.row.col.f32.f16.f16.f32 "
        "{%0,%1,%2,%3}, {%4,%5,%6,%7}, {%8,%9}, {%0,%1,%2,%3};"
        : "+f"(c[0]), "+f"(c[1]), "+f"(c[2]), "+f"(c[3])
        : "r"(a[0]), "r"(a[1]), "r"(a[2]), "r"(a[3]), "r"(b[0]), "r"(b[1]));
}
// A row-major [16 x K] in smem, stride in halves (even), k0 multiple of 16
__device__ __forceinline__ void lda(unsigned* a, const __half* base, int stride,
                                    int k0, int lane) {
    int gr = lane >> 2, gc = lane & 3;
    const __half* p = base + gr * stride + k0 + 2 * gc;
    a[0] = *(const unsigned*)p;
    a[1] = *(const unsigned*)(p + 8 * stride);
    a[2] = *(const unsigned*)(p + 8);
    a[3] = *(const unsigned*)(p + 8 * stride + 8);
}
// B as WT[n][k] row-major (= B col-major), stride in halves
__device__ __forceinline__ void ldb(unsigned* b, const __half* WT, int stride,
                                    int n0, int k0, int lane) {
    int gn = lane >> 2, gc = lane & 3;
    const __half* p = WT + (n0 + gn) * stride + k0 + 2 * gc;
    b[0] = *(const unsigned*)p;
    b[1] = *(const unsigned*)(p + 8);
}

// ------------------- init: pack edges + zero accumulators -------------------
__global__ void k_init(const int* __restrict__ ei, int E, int n) {
    int i = blockIdx.x * blockDim.x + threadIdx.x;
    int stride = gridDim.x * blockDim.x;
    for (int e = i; e < E; e += stride) {
        long eb = 3L * e;
        int s  = __ldg(ei + eb);
        int d  = __ldg(ei + eb + 1);
        int sg = __ldg(ei + eb + 2);
        g_es[e] = make_int2(s, (sg > 0) ? d : ~d);
    }
    uint4 z4 = make_uint4(0u, 0u, 0u, 0u);
    int nh = n * 4;
    for (int j = i; j < nh; j += stride) {
        ((uint4*)g_accPh)[j] = z4;
        ((uint4*)g_accNh)[j] = z4;
    }
    int nd = n * 8;
    for (int j = i; j < nd; j += stride) {
        ((uint4*)g_accP2h)[j] = z4;
        ((uint4*)g_accN2h)[j] = z4;
    }
    int nc = n / 4;
    for (int j = i; j < nc; j += stride) {
        ((uint4*)g_cntp)[j] = z4;
        ((uint4*)g_cntn)[j] = z4;
    }
}

// ----------- projection GEMM (tensor cores): [N x 64] @ [64 x 128] ----------
// reads fp32 x directly; cols 0..31 -> P, 32..63 -> Q, 64..95 -> R(+bp1),
// 96..127 -> S(+bn1)
__global__ void __launch_bounds__(256)
k_projTC(const float* __restrict__ x,
         const float* __restrict__ Wp1, const float* __restrict__ bp1,
         const float* __restrict__ Wn1, const float* __restrict__ bn1,
         int n_nodes, int n_tiles) {
    __shared__ __align__(16) __half WT[128 * 72];
    __shared__ float b1s[64];
    int tid = threadIdx.x;
    for (int i = tid; i < 64 * 128; i += 256) {
        int k = i >> 7, col = i & 127;
        float w;
        if (col < 32)       w = Wp1[k * 32 + col];
        else if (col < 64)  w = Wn1[k * 32 + (col - 32)];
        else if (col < 96)  w = Wp1[(64 + k) * 32 + (col - 64)];
        else                w = Wn1[(64 + k) * 32 + (col - 96)];
        WT[col * 72 + k] = __float2half(w);
    }
    if (tid < 32) { b1s[tid] = bp1[tid]; b1s[32 + tid] = bn1[tid]; }
    __syncthreads();

    int wid = tid >> 5, lane = tid & 31;
    int tile = blockIdx.x * 8 + wid;
    if (tile >= n_tiles) return;
    int base = tile * 16;
    int gr = lane >> 2, gc = lane & 3;
    int r0 = base + gr, r1 = base + gr + 8;
    bool v0 = r0 < n_nodes, v1 = r1 < n_nodes;
    size_t rr0 = v0 ? (size_t)r0 : 0, rr1 = v1 ? (size_t)r1 : 0;

    float c[16][4];
#pragma unroll
    for (int t = 0; t < 16; t++)
        c[t][0] = c[t][1] = c[t][2] = c[t][3] = 0.f;

    for (int kc = 0; kc < 4; kc++) {
        unsigned a[4];
        const float* p0 = x + rr0 * 64 + 16 * kc + 2 * gc;
        const float* p1 = x + rr1 * 64 + 16 * kc + 2 * gc;
        float2 f0 = *(const float2*)p0;
        float2 f1 = *(const float2*)p1;
        float2 f2 = *(const float2*)(p0 + 8);
        float2 f3 = *(const float2*)(p1 + 8);
        a[0] = packh2(f0.x, f0.y);
        a[1] = packh2(f1.x, f1.y);
        a[2] = packh2(f2.x, f2.y);
        a[3] = packh2(f3.x, f3.y);
#pragma unroll
        for (int t = 0; t < 16; t++) {
            unsigned b[2];
            ldb(b, WT, 72, 8 * t, 16 * kc, lane);
            mma16816(c[t], a, b);
        }
    }
#pragma unroll
    for (int t = 0; t < 16; t++) {
        int colw = 8 * t + 2 * gc;
        if (colw < 64) {
            __half* dstb = (colw < 32) ? g_Ph : g_Qh;
            int cw = colw & 31;
            if (v0) *(unsigned*)(dstb + rr0 * 32 + cw) = packh2(c[t][0], c[t][1]);
            if (v1) *(unsigned*)(dstb + rr1 * 32 + cw) = packh2(c[t][2], c[t][3]);
        } else {
            float bb0 = b1s[colw - 64], bb1 = b1s[colw - 63];
            if (v0) *(unsigned*)(g_RSh + rr0 * 64 + (colw - 64)) =
                packh2(c[t][0] + bb0, c[t][1] + bb1);
            if (v1) *(unsigned*)(g_RSh + rr1 * 64 + (colw - 64)) =
                packh2(c[t][2] + bb0, c[t][3] + bb1);
        }
    }
}

// --------------------------- layer-1 aggregation ----------------------------
// 2 edges per thread; 4 chunk-threads per edge pair.
__global__ void k_edge1(int npairs, int E) {
    long idx = (long)blockIdx.x * blockDim.x + threadIdx.x;
    int p = (int)(idx >> 2);
    if (p >= npairs) return;
    int c = (int)(idx & 3);
    int4 es = __ldg((const int4*)g_es + p);
    bool has1 = (2 * p + 1 < E);

    int s0 = es.x, d0 = es.y;
    bool pos0 = (d0 >= 0);
    if (!pos0) d0 = ~d0;
    int s1 = es.z, d1 = es.w;
    bool pos1 = (d1 >= 0);
    if (!pos1) d1 = ~d1;

    uint4 v0 = *((const uint4*)(pos0 ? g_Ph : g_Qh) + (size_t)s0 * 4 + c);
    uint4 v1;
    if (has1) v1 = *((const uint4*)(pos1 ? g_Ph : g_Qh) + (size_t)s1 * 4 + c);

    red_v4h((pos0 ? g_accPh : g_accNh) + (size_t)d0 * 32 + c * 8, v0);
    if (c == 0) atomicAdd(pos0 ? (g_cntp + d0) : (g_cntn + d0), 1.0f);
    if (has1) {
        red_v4h((pos1 ? g_accPh : g_accNh) + (size_t)d1 * 32 + c * 8, v1);
        if (c == 0) atomicAdd(pos1 ? (g_cntp + d1) : (g_cntn + d1), 1.0f);
    }
}

// --------------------- node layer 1: elementwise tanh -----------------------
__global__ void k_node1e(long total) {
    long idx = (long)blockIdx.x * blockDim.x + threadIdx.x;
    if (idx >= total) return;
    int n = (int)(idx >> 3);
    int c = (int)(idx & 7);
    uint4 rs = ((const uint4*)g_RSh)[idx];
    uint4 acc;
    float inv;
    if (c < 4) {
        acc = ((const uint4*)g_accPh)[(size_t)n * 4 + c];
        inv = 1.0f / fmaxf(g_cntp[n], 1.0f);
    } else {
        acc = ((const uint4*)g_accNh)[(size_t)n * 4 + (c - 4)];
        inv = 1.0f / fmaxf(g_cntn[n], 1.0f);
    }
    float rf[8], af[8];
    h8tof(rs, rf);
    h8tof(acc, af);
    uint4 o;
    unsigned* ou = (unsigned*)&o;
#pragma unroll
    for (int j = 0; j < 4; j++)
        ou[j] = packh2(tanhf(rf[2 * j] + af[2 * j] * inv),
                       tanhf(rf[2 * j + 1] + af[2 * j + 1] * inv));
    ((uint4*)g_xpnh)[idx] = o;
}

// --------------------------- layer-2 aggregation ----------------------------
// 2 edges per thread; 8 chunk-threads per edge pair.
__global__ void k_edge2(int npairs, int E) {
    long idx = (long)blockIdx.x * blockDim.x + threadIdx.x;
    int p = (int)(idx >> 3);
    if (p >= npairs) return;
    int c = (int)(idx & 7);
    int4 es = __ldg((const int4*)g_es + p);
    bool has1 = (2 * p + 1 < E);

    int s0 = es.x, d0 = es.y;
    int s1 = es.z, d1 = es.w;

    uint4 v0 = *((const uint4*)g_xpnh + (size_t)s0 * 8 + c);
    uint4 v1;
    if (has1) v1 = *((const uint4*)g_xpnh + (size_t)s1 * 8 + c);

    if (d0 >= 0) {
        red_v4h(g_accP2h + (size_t)d0 * 64 + c * 8, v0);
    } else {
        red_v4h(g_accN2h + (size_t)(~d0) * 64 + (((c + 4) & 7)) * 8, v0);
    }
    if (has1) {
        if (d1 >= 0) {
            red_v4h(g_accP2h + (size_t)d1 * 64 + c * 8, v1);
        } else {
            red_v4h(g_accN2h + (size_t)(~d1) * 64 + (((c + 4) & 7)) * 8, v1);
        }
    }
}

// ------------- node layer 2 + MLP head: tensor-core warp tiles --------------
__global__ void __launch_bounds__(256)
k_node2TC(const float* __restrict__ Wp2, const float* __restrict__ bp2,
          const float* __restrict__ Wn2, const float* __restrict__ bn2,
          const float* __restrict__ Ww,  const float* __restrict__ bw,
          const float* __restrict__ Wm1, const float* __restrict__ bm1,
          const float* __restrict__ g1,  const float* __restrict__ be1,
          const float* __restrict__ rm1, const float* __restrict__ rv1,
          const float* __restrict__ Wm2, const float* __restrict__ bm2,
          const float* __restrict__ g2,  const float* __restrict__ be2,
          const float* __restrict__ rm2, const float* __restrict__ rv2,
          const float* __restrict__ Wm3, const float* __restrict__ bm3,
          float* __restrict__ outz, float* __restrict__ outp,
          int n_nodes, int n_tiles) {
    extern __shared__ __align__(16) __half smh[];
    __half* WpT = smh;                    // 32 x 104
    __half* WnT = smh + 3328;             // 32 x 104
    __half* WwT = smh + 6656;             // 64 x 72
    __half* W1T = smh + 11264;            // 64 x 72
    __half* W2T = smh + 15872;            // 64 x 72
    float* fb = (float*)(smh + 56320);
    float* bp2s = fb;         // 32
    float* bn2s = fb + 32;    // 32
    float* bws  = fb + 64;    // 64
    float* sc1  = fb + 128;   // 64
    float* of1  = fb + 192;   // 64
    float* sc2  = fb + 256;   // 64
    float* of2  = fb + 320;   // 64
    float* w3s  = fb + 384;   // 64
    // fb[448] = b3

    int tid = threadIdx.x;
    for (int i = tid; i < 96 * 32; i += 256) {
        int k = i >> 5, nn = i & 31;
        WpT[nn * 104 + k] = __float2half(Wp2[i]);
        WnT[nn * 104 + k] = __float2half(Wn2[i]);
    }
    for (int i = tid; i < 64 * 64; i += 256) {
        int k = i >> 6, nn = i & 63;
        WwT[nn * 72 + k] = __float2half(Ww[i]);
        W1T[nn * 72 + k] = __float2half(Wm1[i]);
        W2T[nn * 72 + k] = __float2half(Wm2[i]);
    }
    if (tid < 32) { bp2s[tid] = bp2[tid]; bn2s[tid] = bn2[tid]; }
    if (tid < 64) {
        bws[tid] = bw[tid];
        float s1 = g1[tid] * rsqrtf(rv1[tid] + 1e-5f);
        sc1[tid] = s1;
        of1[tid] = (bm1[tid] - rm1[tid]) * s1 + be1[tid];
        float s2 = g2[tid] * rsqrtf(rv2[tid] + 1e-5f);
        sc2[tid] = s2;
        of2[tid] = (bm2[tid] - rm2[tid]) * s2 + be2[tid];
        w3s[tid] = Wm3[tid];
    }
    if (tid == 0) fb[448] = bm3[0];
    __syncthreads();

    int wid = tid >> 5, lane = tid & 31;
    __half* Ahp = smh + 20480 + wid * 1664;  // 16 x 104
    __half* Ahn = smh + 33792 + wid * 1664;  // 16 x 104
    __half* zs  = smh + 47104 + wid * 1152;  // 16 x 72

    int tile = blockIdx.x * 8 + wid;
    if (tile >= n_tiles) return;
    int base = tile * 16;
    int gr = lane >> 2, gc = lane & 3;

    // ---- stage scaled inputs ----
    {
        int row = lane >> 1, part = lane & 1;
        int n = base + row;
        if (n >= n_nodes) n = n_nodes - 1;
        __half2 ivp = __float2half2_rn(1.0f / fmaxf(g_cntp[n], 1.0f));
        __half2 ivn = __float2half2_rn(1.0f / fmaxf(g_cntn[n], 1.0f));
        const uint4* sp = (const uint4*)g_accP2h + (size_t)n * 8;
        const uint4* sn = (const uint4*)g_accN2h + (size_t)n * 8;
        const uint4* sx = (const uint4*)g_xpnh + (size_t)n * 8;
        uint4* rp = (uint4*)(Ahp + row * 104);
        uint4* rn = (uint4*)(Ahn + row * 104);
        if (part == 0) {
#pragma unroll
            for (int j = 0; j < 4; j++) {
                rp[j] = scale8(sp[j], ivp);       // A
                rn[j] = scale8(sp[4 + j], ivp);   // C
            }
            rp[4] = scale8(sn[0], ivn); rp[5] = scale8(sn[1], ivn);  // B lo
            rn[4] = scale8(sn[4], ivn); rn[5] = scale8(sn[5], ivn);  // D lo
        } else {
            rp[6] = scale8(sn[2], ivn); rp[7] = scale8(sn[3], ivn);  // B hi
            rn[6] = scale8(sn[6], ivn); rn[7] = scale8(sn[7], ivn);  // D hi
#pragma unroll
            for (int j = 0; j < 4; j++) {
                rp[8 + j] = sx[j];        // xp
                rn[8 + j] = sx[4 + j];    // xn
            }
        }
    }
    __syncwarp();

    // ---- loop1: hp (t 0..3), hn (t 4..7), K = 96 ----
    float c1[8][4];
#pragma unroll
    for (int t = 0; t < 8; t++)
        c1[t][0] = c1[t][1] = c1[t][2] = c1[t][3] = 0.f;
    for (int kc = 0; kc < 6; kc++) {
        unsigned a[4], b[2];
        lda(a, Ahp, 104, 16 * kc, lane);
#pragma unroll
        for (int t = 0; t < 4; t++) {
            ldb(b, WpT, 104, 8 * t, 16 * kc, lane);
            mma16816(c1[t], a, b);
        }
        lda(a, Ahn, 104, 16 * kc, lane);
#pragma unroll
        for (int t = 0; t < 4; t++) {
            ldb(b, WnT, 104, 8 * t, 16 * kc, lane);
            mma16816(c1[4 + t], a, b);
        }
    }
    __syncwarp();
#pragma unroll
    for (int t = 0; t < 8; t++) {
        int c32 = 8 * (t & 3) + 2 * gc;
        const float* barr = (t < 4) ? bp2s : bn2s;
        float b0 = barr[c32], b1 = barr[c32 + 1];
        int cz = (t < 4) ? c32 : 32 + c32;
        *(unsigned*)(zs + gr * 72 + cz) =
            packh2(tanhf(c1[t][0] + b0), tanhf(c1[t][1] + b1));
        *(unsigned*)(zs + (gr + 8) * 72 + cz) =
            packh2(tanhf(c1[t][2] + b0), tanhf(c1[t][3] + b1));
    }
    __syncwarp();

    int nr0 = base + gr, nr1 = base + gr + 8;
    bool v0 = nr0 < n_nodes, v1 = nr1 < n_nodes;

    // ---- loop2: z = tanh(z2 @ Ww + bw) ----
    float c2[8][4];
#pragma unroll
    for (int t = 0; t < 8; t++)
        c2[t][0] = c2[t][1] = c2[t][2] = c2[t][3] = 0.f;
    for (int kc = 0; kc < 4; kc++) {
        unsigned a[4], b[2];
        lda(a, zs, 72, 16 * kc, lane);
#pragma unroll
        for (int t = 0; t < 8; t++) {
            ldb(b, WwT, 72, 8 * t, 16 * kc, lane);
            mma16816(c2[t], a, b);
        }
    }
    __syncwarp();
#pragma unroll
    for (int t = 0; t < 8; t++) {
        int col = 8 * t + 2 * gc;
        float z0 = tanhf(c2[t][0] + bws[col]);
        float z1 = tanhf(c2[t][1] + bws[col + 1]);
        float z2v = tanhf(c2[t][2] + bws[col]);
        float z3 = tanhf(c2[t][3] + bws[col + 1]);
        if (v0) *(float2*)(outz + (size_t)nr0 * 64 + col) = make_float2(z0, z1);
        if (v1) *(float2*)(outz + (size_t)nr1 * 64 + col) = make_float2(z2v, z3);
        *(unsigned*)(zs + gr * 72 + col) = packh2(z0, z1);
        *(unsigned*)(zs + (gr + 8) * 72 + col) = packh2(z2v, z3);
    }
    __syncwarp();

    // ---- loop3: h = relu(bn1(z @ Wm1)) ----
#pragma unroll
    for (int t = 0; t < 8; t++)
        c2[t][0] = c2[t][1] = c2[t][2] = c2[t][3] = 0.f;
    for (int kc = 0; kc < 4; kc++) {
        unsigned a[4], b[2];
        lda(a, zs, 72, 16 * kc, lane);
#pragma unroll
        for (int t = 0; t < 8; t++) {
            ldb(b, W1T, 72, 8 * t, 16 * kc, lane);
            mma16816(c2[t], a, b);
        }
    }
    __syncwarp();
#pragma unroll
    for (int t = 0; t < 8; t++) {
        int col = 8 * t + 2 * gc;
        float h0 = fmaxf(c2[t][0] * sc1[col] + of1[col], 0.f);
        float h1 = fmaxf(c2[t][1] * sc1[col + 1] + of1[col + 1], 0.f);
        float h2 = fmaxf(c2[t][2] * sc1[col] + of1[col], 0.f);
        float h3 = fmaxf(c2[t][3] * sc1[col + 1] + of1[col + 1], 0.f);
        *(unsigned*)(zs + gr * 72 + col) = packh2(h0, h1);
        *(unsigned*)(zs + (gr + 8) * 72 + col) = packh2(h2, h3);
    }
    __syncwarp();

    // ---- loop4: r = relu(bn2(h @ Wm2)); prob = sigmoid(r.w3 + b3) ----
#pragma unroll
    for (int t = 0; t < 8; t++)
        c2[t][0] = c2[t][1] = c2[t][2] = c2[t][3] = 0.f;
    for (int kc = 0; kc < 4; kc++) {
        unsigned a[4], b[2];
        lda(a, zs, 72, 16 * kc, lane);
#pragma unroll
        for (int t = 0; t < 8; t++) {
            ldb(b, W2T, 72, 8 * t, 16 * kc, lane);
            mma16816(c2[t], a, b);
        }
    }
    float p0 = 0.f, p1 = 0.f;
#pragma unroll
    for (int t = 0; t < 8; t++) {
        int col = 8 * t + 2 * gc;
        float r0 = fmaxf(c2[t][0] * sc2[col] + of2[col], 0.f);
        float r1 = fmaxf(c2[t][1] * sc2[col + 1] + of2[col + 1], 0.f);
        float r2 = fmaxf(c2[t][2] * sc2[col] + of2[col], 0.f);
        float r3 = fmaxf(c2[t][3] * sc2[col + 1] + of2[col + 1], 0.f);
        p0 += r0 * w3s[col] + r1 * w3s[col + 1];
        p1 += r2 * w3s[col] + r3 * w3s[col + 1];
    }
    p0 += __shfl_xor_sync(0xffffffffu, p0, 1);
    p0 += __shfl_xor_sync(0xffffffffu, p0, 2);
    p1 += __shfl_xor_sync(0xffffffffu, p1, 1);
    p1 += __shfl_xor_sync(0xffffffffu, p1, 2);
    if ((lane & 3) == 0) {
        float b3 = fb[448];
        if (v0) outp[nr0] = 1.0f / (1.0f + expf(-(p0 + b3)));
        if (v1) outp[nr1] = 1.0f / (1.0f + expf(-(p1 + b3)));
    }
}

// -------------------------------- launcher ----------------------------------
extern "C" void kernel_launch(void* const* d_in, const int* in_sizes, int n_in,
                              void* d_out, int out_size) {
    const float* x   = (const float*)d_in[0];
    const int*   ei  = (const int*)d_in[1];
    const float* Wp1 = (const float*)d_in[2];
    const float* bp1 = (const float*)d_in[3];
    const float* Wn1 = (const float*)d_in[4];
    const float* bn1 = (const float*)d_in[5];
    const float* Wp2 = (const float*)d_in[6];
    const float* bp2 = (const float*)d_in[7];
    const float* Wn2 = (const float*)d_in[8];
    const float* bn2 = (const float*)d_in[9];
    const float* Ww  = (const float*)d_in[10];
    const float* bw  = (const float*)d_in[11];
    const float* Wm1 = (const float*)d_in[12];
    const float* bm1 = (const float*)d_in[13];
    const float* g1  = (const float*)d_in[14];
    const float* be1 = (const float*)d_in[15];
    const float* rm1 = (const float*)d_in[16];
    const float* rv1 = (const float*)d_in[17];
    const float* Wm2 = (const float*)d_in[18];
    const float* bm2 = (const float*)d_in[19];
    const float* g2  = (const float*)d_in[20];
    const float* be2 = (const float*)d_in[21];
    const float* rm2 = (const float*)d_in[22];
    const float* rv2 = (const float*)d_in[23];
    const float* Wm3 = (const float*)d_in[24];
    const float* bm3 = (const float*)d_in[25];

    int Nn = in_sizes[0] / DD;
    int E  = in_sizes[1] / 3;

    float* out  = (float*)d_out;
    float* outz = out;
    float* outp = out + (size_t)Nn * DD;

    int n_tiles = (Nn + 15) / 16;
    int n_blks  = (n_tiles + 7) / 8;
    int npairs  = (E + 1) / 2;

    const int NODE2_SMEM = 56320 * 2 + 452 * 4;  // 114448 B
    cudaFuncSetAttribute(k_node2TC, cudaFuncAttributeMaxDynamicSharedMemorySize,
                         NODE2_SMEM);

    k_init<<<2048, 256>>>(ei, E, Nn);

    k_projTC<<<n_blks, 256>>>(x, Wp1, bp1, Wn1, bn1, Nn, n_tiles);

    long t1 = (long)npairs * 4;
    k_edge1<<<(int)((t1 + 255) / 256), 256>>>(npairs, E);

    long tn = (long)Nn * 8;
    k_node1e<<<(int)((tn + 255) / 256), 256>>>(tn);

    long t2 = (long)npairs * 8;
    k_edge2<<<(int)((t2 + 255) / 256), 256>>>(npairs, E);

    k_node2TC<<<n_blks, 256, NODE2_SMEM>>>(
        Wp2, bp2, Wn2, bn2, Ww, bw,
        Wm1, bm1, g1, be1, rm1, rv1,
        Wm2, bm2, g2, be2, rm2, rv2,
        Wm3, bm3, outz, outp, Nn, n_tiles);
}